// round 16
// baseline (speedup 1.0000x reference)
#include <cuda_runtime.h>
#include <cuda_fp16.h>
#include <cstdint>

// ---------------------------------------------------------------------------
// FeatureIntegration: gather+pad -> SE gate -> GEMM (32768x1536 @ 1536x256)
// Round 16: R15 kernels (GEMM measured AT the mma.sync MAC roofline ~89us)
// + stream fork-join overlap: rows split into halves, gatea(half1) runs
// concurrently with gemm(half0), hiding ~21us of DRAM work under MAC-bound
// GEMM. Kernels byte-identical to R15 except a base-offset parameter.
// ---------------------------------------------------------------------------

#define N_ENT    32
#define C_DIM    64
#define OUT_DIM  256
#define LEN_M    16
#define LEN_L    8
#define B_SZ     1024
#define ROWS_TOT (B_SZ * N_ENT)     // 32768

#define KT_TILES 48                 // K32 image tiles (storage layout)
#define TT       24                 // K64 compute iterations

// smem u32 offsets: 3 stages x (A 4096 + B 4096)
#define SM_STAGE 8192
#define SM_U32   24576              // 98304 bytes

__device__ unsigned g_a[(size_t)256 * KT_TILES * 2048];     // 100.7 MB A images
__device__ unsigned g_wt[2 * KT_TILES * 128 * 16];          // 786 KB B images

__device__ __forceinline__ uint32_t smem_u32(const void* p) {
    uint32_t a;
    asm("{ .reg .u64 t; cvta.to.shared.u64 t, %1; cvt.u32.u64 %0, t; }"
        : "=r"(a) : "l"(p));
    return a;
}

__device__ __forceinline__ void cp16(uint32_t dst, const void* src) {
    asm volatile("cp.async.cg.shared.global [%0], [%1], 16;"
                 :: "r"(dst), "l"(src) : "memory");
}
#define CP_COMMIT() asm volatile("cp.async.commit_group;" ::: "memory")
#define CP_WAIT(N)  asm volatile("cp.async.wait_group %0;" :: "n"(N) : "memory")

__device__ __forceinline__ uint32_t pack2(float lo, float hi) {
    __half2 h = __floats2half2_rn(lo, hi);   // .x = lo (lower k), .y = hi
    return *(uint32_t*)&h;
}

__device__ __forceinline__ void mma_f16(float* d, const uint32_t* a, const uint32_t* b) {
    asm volatile(
        "mma.sync.aligned.m16n8k16.row.col.f32.f16.f16.f32 "
        "{%0,%1,%2,%3}, {%4,%5,%6,%7}, {%8,%9}, {%0,%1,%2,%3};"
        : "+f"(d[0]), "+f"(d[1]), "+f"(d[2]), "+f"(d[3])
        : "r"(a[0]), "r"(a[1]), "r"(a[2]), "r"(a[3]), "r"(b[0]), "r"(b[1]));
}

// ---------------------------------------------------------------------------
// Kernel 1: fused SE gate + A-image emit (R15 + bn_base offset).
// ---------------------------------------------------------------------------
__global__ __launch_bounds__(128)
void gatea_kernel(const float* __restrict__ xm,
                  const float* __restrict__ xl,
                  const float* __restrict__ w1,   // (4,64)
                  const float* __restrict__ w2,   // (64,4)
                  int bn_base)
{
    const int tid = threadIdx.x;
    const int j   = tid & 15;
    const int bn  = bn_base + blockIdx.x * 8 + (tid >> 4);
    const int b   = bn >> 5;
    const int n   = bn & 31;

    float4 xv[24];
    const float4* pm = (const float4*)(xm
        + ((size_t)(b * (N_ENT * LEN_M) + n * LEN_M)) * C_DIM) + j;
#pragma unroll
    for (int t = 0; t < LEN_M; t++) xv[t] = pm[t * 16];
    const float4* pl = (const float4*)(xl
        + ((size_t)(b * (N_ENT * LEN_L) + n * LEN_L)) * C_DIM) + j;
#pragma unroll
    for (int t = 0; t < LEN_L; t++) xv[LEN_M + t] = pl[t * 16];

    float4 s = make_float4(0.f, 0.f, 0.f, 0.f);
#pragma unroll
    for (int t = 0; t < 24; t++) {
        s.x += xv[t].x; s.y += xv[t].y; s.z += xv[t].z; s.w += xv[t].w;
    }
    const float inv = 1.0f / 32.0f;
    s.x *= inv; s.y *= inv; s.z *= inv; s.w *= inv;

    float h[4];
#pragma unroll
    for (int i = 0; i < 4; i++) {
        float4 w = *(const float4*)(w1 + i * C_DIM + j * 4);
        h[i] = s.x * w.x + s.y * w.y + s.z * w.z + s.w * w.w;
    }
#pragma unroll
    for (int off = 8; off; off >>= 1)
#pragma unroll
        for (int i = 0; i < 4; i++)
            h[i] += __shfl_xor_sync(0xFFFFFFFFu, h[i], off);
#pragma unroll
    for (int i = 0; i < 4; i++) h[i] = fmaxf(h[i], 0.f);

    float4 g4;
#pragma unroll
    for (int q = 0; q < 4; q++) {
        int c = j * 4 + q;
        float4 w = *(const float4*)(w2 + c * 4);
        float z = h[0] * w.x + h[1] * w.y + h[2] * w.z + h[3] * w.w;
        ((float*)&g4)[q] = 1.0f / (1.0f + __expf(-z));
    }

    const int r   = bn & 127;
    const int rb  = bn >> 7;
    const int xr  = (r >> 1) & 3;
    const int c4  = j & 7;
    const int q0  = (2 * c4) & 3;
    const int off = c4 >> 1;
    const int a0  = ((q0      ^ xr) << 2) + off;
    const int a1  = (((q0 | 1) ^ xr) << 2) + off;
    const int ktb = j >> 3;
#pragma unroll
    for (int t = 0; t < 24; t++) {
        unsigned* base = g_a + ((size_t)(rb * KT_TILES + 2 * t + ktb)) * 2048 + r * 16;
        float4 v = xv[t];
        base[a0] = pack2(v.x * g4.x, v.y * g4.y);
        base[a1] = pack2(v.z * g4.z, v.w * g4.w);
    }
}

// ---------------------------------------------------------------------------
// Kernel 2: W prep -> fp16 swizzled tile images (unchanged).
// ---------------------------------------------------------------------------
__global__ __launch_bounds__(256)
void wprep_kernel(const float* __restrict__ aw)
{
    int gid = blockIdx.x * 256 + threadIdx.x;     // 49152 granules
    int gp  = gid & 3;
    int n   = (gid >> 2) & 127;
    int hk  = gid >> 9;                           // h*48 + kt
    int kt  = hk % 48;
    int h   = hk / 48;
    int o   = h * 128 + n;
    int gl  = gp ^ ((n >> 1) & 3);

    uint4 v;
#pragma unroll
    for (int j = 0; j < 4; j++) {
        int u = 4 * j + gl;
        int f = kt * 32 + 2 * u + (kt >= 32 ? 256 : 0);
        ((uint32_t*)&v)[j] = pack2(aw[(size_t)o * 2048 + f],
                                   aw[(size_t)o * 2048 + f + 1]);
    }
    ((uint4*)g_wt)[gid] = v;
}

// ---------------------------------------------------------------------------
// Kernel 3: streaming fp16 GEMM, K-tile 64 (R15 + rb_base offset).
// ---------------------------------------------------------------------------
__global__ __launch_bounds__(128, 2)
void gemm_mma(const float* __restrict__ bias,
              float* __restrict__ out,
              int rb_base)
{
    extern __shared__ uint32_t smu[];
    const uint32_t sb = smem_u32(smu);

    const int tid  = threadIdx.x;
    const int lane = tid & 31;
    const int wid  = tid >> 5;
    const int tig  = lane & 3;
    const int grp  = lane >> 2;
    const int wrow = (wid >> 1) * 64;
    const int wcol = (wid & 1) * 64;
    const int rb       = rb_base + blockIdx.x;    // row block
    const int row_base = rb * 128;
    const int h        = blockIdx.y;              // col half
    const int col_base = h * 128;

    const uint4* a_base = (const uint4*)(g_a + (size_t)rb * KT_TILES * 2048);
    const uint4* b_base = (const uint4*)g_wt + (size_t)h * KT_TILES * 512;

    auto cp_tile = [&](int tt, int st) {
        uint32_t dst = sb + (st * SM_STAGE) * 4;
        const uint4* sa  = a_base + (size_t)tt * 1024;
        const uint4* sbp = b_base + (size_t)tt * 1024;
#pragma unroll
        for (int i = 0; i < 8; i++) {
            int gi = i * 128 + tid;
            cp16(dst + gi * 16, sa + gi);
        }
#pragma unroll
        for (int i = 0; i < 8; i++) {
            int gi = i * 128 + tid;
            cp16(dst + 16384 + gi * 16, sbp + gi);
        }
    };

    cp_tile(0, 0); CP_COMMIT();
    cp_tile(1, 1); CP_COMMIT();

    float acc[4][8][4];
#pragma unroll
    for (int mt = 0; mt < 4; mt++)
#pragma unroll
        for (int nt = 0; nt < 8; nt++)
#pragma unroll
            for (int q = 0; q < 4; q++) acc[mt][nt][q] = 0.f;

    CP_WAIT(1);
    __syncthreads();

    for (int tt = 0; tt < TT; tt++) {
        const int st = tt % 3;
        if (tt + 2 < TT) {
            cp_tile(tt + 2, (tt + 2) % 3);
            CP_COMMIT();
        }

#pragma unroll
        for (int sub = 0; sub < 2; sub++) {
            const uint32_t* AS = smu + st * SM_STAGE + sub * 2048;
            const uint32_t* BS = smu + st * SM_STAGE + 4096 + sub * 2048;
            uint32_t afA[4][4], afB[4][4];
#pragma unroll
            for (int mt = 0; mt < 4; mt++) {
                int r = wrow + mt * 16 + grp;
                int pg = (tig ^ ((r >> 1) & 3)) * 4;
                *(uint4*)&afA[mt][0] = *(const uint4*)&AS[r * 16 + pg];
                *(uint4*)&afB[mt][0] = *(const uint4*)&AS[(r + 8) * 16 + pg];
            }
            uint32_t bf[8][4];
#pragma unroll
            for (int nt = 0; nt < 8; nt++) {
                int n = wcol + nt * 8 + grp;
                int pg = (tig ^ ((n >> 1) & 3)) * 4;
                *(uint4*)&bf[nt][0] = *(const uint4*)&BS[n * 16 + pg];
            }
#pragma unroll
            for (int s = 0; s < 2; s++) {
#pragma unroll
                for (int mt = 0; mt < 4; mt++) {
                    uint32_t a[4] = { afA[mt][2 * s], afB[mt][2 * s],
                                      afA[mt][2 * s + 1], afB[mt][2 * s + 1] };
#pragma unroll
                    for (int nt = 0; nt < 8; nt++) {
                        uint32_t b[2] = { bf[nt][2 * s], bf[nt][2 * s + 1] };
                        mma_f16(acc[mt][nt], a, b);
                    }
                }
            }
        }

        if (tt + 2 < TT) { CP_WAIT(1); } else { CP_WAIT(0); }
        __syncthreads();
    }

#pragma unroll
    for (int mt = 0; mt < 4; mt++) {
        int gr = row_base + wrow + mt * 16 + grp;
#pragma unroll
        for (int nt = 0; nt < 8; nt++) {
            int gc = col_base + wcol + nt * 8 + tig * 2;
            float2 bb = *(const float2*)&bias[gc];
            float2 v0; v0.x = acc[mt][nt][0] + bb.x; v0.y = acc[mt][nt][1] + bb.y;
            *(float2*)&out[(size_t)gr * OUT_DIM + gc] = v0;
            float2 v1; v1.x = acc[mt][nt][2] + bb.x; v1.y = acc[mt][nt][3] + bb.y;
            *(float2*)&out[(size_t)(gr + 8) * OUT_DIM + gc] = v1;
        }
    }
}

// ---------------------------------------------------------------------------
// Launch: fork-join overlap. Streams/events are host objects, created once
// on the first (pre-capture correctness) call; every call issues the same
// launch DAG, which is graph-capturable via the standard event fork-join.
//   stream0: wprep -> gatea(h0) -> [ev0] -> gemm(h0) -> [wait ev1] -> gemm(h1)
//   s1:      [wait ev0] -> gatea(h1) -> [ev1]
// ---------------------------------------------------------------------------
static cudaStream_t g_s1;
static cudaEvent_t  g_ev0, g_ev1;

static void streams_init_once()
{
    static bool done = false;
    if (!done) {
        cudaStreamCreateWithFlags(&g_s1, cudaStreamNonBlocking);
        cudaEventCreateWithFlags(&g_ev0, cudaEventDisableTiming);
        cudaEventCreateWithFlags(&g_ev1, cudaEventDisableTiming);
        done = true;
    }
}

extern "C" void kernel_launch(void* const* d_in, const int* in_sizes, int n_in,
                              void* d_out, int out_size)
{
    const float* xm = (const float*)d_in[0];
    const float* xl = (const float*)d_in[1];
    const float* w1 = (const float*)d_in[3];
    const float* w2 = (const float*)d_in[4];
    const float* aw = (const float*)d_in[5];
    const float* ab = (const float*)d_in[6];
    float* out = (float*)d_out;

    streams_init_once();

    const int smem_bytes = SM_U32 * 4;   // 98304
    cudaFuncSetAttribute(gemm_mma, cudaFuncAttributeMaxDynamicSharedMemorySize, smem_bytes);

    const int half_blocks = (ROWS_TOT / 2) / 8;    // 2048 gatea blocks per half
    dim3 ggrid(128, 2);                            // gemm grid per half

    // stream0: wprep, gatea half0
    wprep_kernel<<<(2 * KT_TILES * 128 * 4) / 256, 256, 0, 0>>>(aw);
    gatea_kernel<<<half_blocks, 128, 0, 0>>>(xm, xl, w1, w2, 0);
    cudaEventRecord(g_ev0, 0);

    // s1: gatea half1 (starts when half0 done; runs concurrent with gemm h0)
    cudaStreamWaitEvent(g_s1, g_ev0, 0);
    gatea_kernel<<<half_blocks, 128, 0, g_s1>>>(xm, xl, w1, w2, ROWS_TOT / 2);
    cudaEventRecord(g_ev1, g_s1);

    // stream0: gemm half0 (overlaps gatea half1), then join, then gemm half1
    gemm_mma<<<ggrid, 128, smem_bytes, 0>>>(ab, out, 0);
    cudaStreamWaitEvent(0, g_ev1, 0);
    gemm_mma<<<ggrid, 128, smem_bytes, 0>>>(ab, out, 128);
}

// round 17
// speedup vs baseline: 1.0569x; 1.0569x over previous
#include <cuda_runtime.h>
#include <cuda_fp16.h>
#include <cstdint>

// ---------------------------------------------------------------------------
// FeatureIntegration: gather+pad -> SE gate -> GEMM (32768x1536 @ 1536x256)
// Round 17: R15 pipeline (134us) with a 128x64 CTA tile (4 warps, warp tile
// 64x32, acc 64 regs) -> 3 CTAs/SM = 12 warps/SM (was 8). R16 showed the
// gemm at only 48.8% tensor with occ 10.6%; this raises issue-slot coverage
// without spill risk. Streams overlap reverted (proven non-concurrent).
// ---------------------------------------------------------------------------

#define N_ENT    32
#define C_DIM    64
#define OUT_DIM  256
#define LEN_M    16
#define LEN_L    8
#define B_SZ     1024
#define ROWS_TOT (B_SZ * N_ENT)     // 32768

#define KT_TILES 48                 // K32 image tiles (storage layout)
#define TT       24                 // K64 compute iterations

// smem u32 layout per stage: A 4096 (16KB) | Bk0 1024 (4KB) | Bk1 1024 (4KB)
#define SM_STAGE 6144               // 24KB per stage
#define SM_U32   18432              // 3 stages = 73728 bytes

__device__ unsigned g_a[(size_t)256 * KT_TILES * 2048];     // 100.7 MB A images
__device__ unsigned g_wt[2 * KT_TILES * 128 * 16];          // 786 KB B images

__device__ __forceinline__ uint32_t smem_u32(const void* p) {
    uint32_t a;
    asm("{ .reg .u64 t; cvta.to.shared.u64 t, %1; cvt.u32.u64 %0, t; }"
        : "=r"(a) : "l"(p));
    return a;
}

__device__ __forceinline__ void cp16(uint32_t dst, const void* src) {
    asm volatile("cp.async.cg.shared.global [%0], [%1], 16;"
                 :: "r"(dst), "l"(src) : "memory");
}
#define CP_COMMIT() asm volatile("cp.async.commit_group;" ::: "memory")
#define CP_WAIT(N)  asm volatile("cp.async.wait_group %0;" :: "n"(N) : "memory")

__device__ __forceinline__ uint32_t pack2(float lo, float hi) {
    __half2 h = __floats2half2_rn(lo, hi);   // .x = lo (lower k), .y = hi
    return *(uint32_t*)&h;
}

__device__ __forceinline__ void mma_f16(float* d, const uint32_t* a, const uint32_t* b) {
    asm volatile(
        "mma.sync.aligned.m16n8k16.row.col.f32.f16.f16.f32 "
        "{%0,%1,%2,%3}, {%4,%5,%6,%7}, {%8,%9}, {%0,%1,%2,%3};"
        : "+f"(d[0]), "+f"(d[1]), "+f"(d[2]), "+f"(d[3])
        : "r"(a[0]), "r"(a[1]), "r"(a[2]), "r"(a[3]), "r"(b[0]), "r"(b[1]));
}

// ---------------------------------------------------------------------------
// Kernel 1: fused SE gate + A-image emit (byte-identical to R15; at roofline).
// ---------------------------------------------------------------------------
__global__ __launch_bounds__(128)
void gatea_kernel(const float* __restrict__ xm,
                  const float* __restrict__ xl,
                  const float* __restrict__ w1,   // (4,64)
                  const float* __restrict__ w2)   // (64,4)
{
    const int tid = threadIdx.x;
    const int j   = tid & 15;
    const int bn  = blockIdx.x * 8 + (tid >> 4);
    const int b   = bn >> 5;
    const int n   = bn & 31;

    float4 xv[24];
    const float4* pm = (const float4*)(xm
        + ((size_t)(b * (N_ENT * LEN_M) + n * LEN_M)) * C_DIM) + j;
#pragma unroll
    for (int t = 0; t < LEN_M; t++) xv[t] = pm[t * 16];
    const float4* pl = (const float4*)(xl
        + ((size_t)(b * (N_ENT * LEN_L) + n * LEN_L)) * C_DIM) + j;
#pragma unroll
    for (int t = 0; t < LEN_L; t++) xv[LEN_M + t] = pl[t * 16];

    float4 s = make_float4(0.f, 0.f, 0.f, 0.f);
#pragma unroll
    for (int t = 0; t < 24; t++) {
        s.x += xv[t].x; s.y += xv[t].y; s.z += xv[t].z; s.w += xv[t].w;
    }
    const float inv = 1.0f / 32.0f;
    s.x *= inv; s.y *= inv; s.z *= inv; s.w *= inv;

    float h[4];
#pragma unroll
    for (int i = 0; i < 4; i++) {
        float4 w = *(const float4*)(w1 + i * C_DIM + j * 4);
        h[i] = s.x * w.x + s.y * w.y + s.z * w.z + s.w * w.w;
    }
#pragma unroll
    for (int off = 8; off; off >>= 1)
#pragma unroll
        for (int i = 0; i < 4; i++)
            h[i] += __shfl_xor_sync(0xFFFFFFFFu, h[i], off);
#pragma unroll
    for (int i = 0; i < 4; i++) h[i] = fmaxf(h[i], 0.f);

    float4 g4;
#pragma unroll
    for (int q = 0; q < 4; q++) {
        int c = j * 4 + q;
        float4 w = *(const float4*)(w2 + c * 4);
        float z = h[0] * w.x + h[1] * w.y + h[2] * w.z + h[3] * w.w;
        ((float*)&g4)[q] = 1.0f / (1.0f + __expf(-z));
    }

    const int r   = bn & 127;
    const int rb  = bn >> 7;
    const int xr  = (r >> 1) & 3;
    const int c4  = j & 7;
    const int q0  = (2 * c4) & 3;
    const int off = c4 >> 1;
    const int a0  = ((q0      ^ xr) << 2) + off;
    const int a1  = (((q0 | 1) ^ xr) << 2) + off;
    const int ktb = j >> 3;
#pragma unroll
    for (int t = 0; t < 24; t++) {
        unsigned* base = g_a + ((size_t)(rb * KT_TILES + 2 * t + ktb)) * 2048 + r * 16;
        float4 v = xv[t];
        base[a0] = pack2(v.x * g4.x, v.y * g4.y);
        base[a1] = pack2(v.z * g4.z, v.w * g4.w);
    }
}

// ---------------------------------------------------------------------------
// Kernel 2: W prep -> fp16 swizzled tile images (unchanged).
// ---------------------------------------------------------------------------
__global__ __launch_bounds__(256)
void wprep_kernel(const float* __restrict__ aw)
{
    int gid = blockIdx.x * 256 + threadIdx.x;     // 49152 granules
    int gp  = gid & 3;
    int n   = (gid >> 2) & 127;
    int hk  = gid >> 9;                           // h*48 + kt
    int kt  = hk % 48;
    int h   = hk / 48;
    int o   = h * 128 + n;
    int gl  = gp ^ ((n >> 1) & 3);

    uint4 v;
#pragma unroll
    for (int j = 0; j < 4; j++) {
        int u = 4 * j + gl;
        int f = kt * 32 + 2 * u + (kt >= 32 ? 256 : 0);
        ((uint32_t*)&v)[j] = pack2(aw[(size_t)o * 2048 + f],
                                   aw[(size_t)o * 2048 + f + 1]);
    }
    ((uint4*)g_wt)[gid] = v;
}

// ---------------------------------------------------------------------------
// Kernel 3: streaming fp16 GEMM. CTA 128 rows x 64 cols, 4 warps (64x32),
// acc 64 regs -> 3 CTAs/SM. K-tile 64, 3-stage cp.async ring, 1 sync/iter.
// grid = (256 row-blocks, 4 col-quarters). Fragment math = R12-verified;
// B sub-slab local row keeps the XOR key valid (64 = 0 mod 4).
// ---------------------------------------------------------------------------
__global__ __launch_bounds__(128, 3)
void gemm_mma(const float* __restrict__ bias,
              float* __restrict__ out)
{
    extern __shared__ uint32_t smu[];
    const uint32_t sb = smem_u32(smu);

    const int tid  = threadIdx.x;
    const int lane = tid & 31;
    const int wid  = tid >> 5;
    const int tig  = lane & 3;
    const int grp  = lane >> 2;
    const int wrow = (wid >> 1) * 64;             // 0 or 64
    const int wcol = (wid & 1) * 32;              // 0 or 32
    const int rb       = blockIdx.x;              // row block (128 rows)
    const int row_base = rb * 128;
    const int q        = blockIdx.y;              // col quarter (64 cols)
    const int col_base = q * 64;
    const int h  = q >> 1;                        // which B image half
    const int nh = (q & 1) * 64;                  // row offset within image

    const uint4* a_base = (const uint4*)(g_a + (size_t)rb * KT_TILES * 2048);

    // one K64 tile: A 16KB (contiguous) + B two 4KB slabs (kt0, kt1)
    auto cp_tile = [&](int tt, int st) {
        uint32_t dst = sb + (st * SM_STAGE) * 4;
        const uint4* sa = a_base + (size_t)tt * 1024;
#pragma unroll
        for (int i = 0; i < 8; i++) {
            int gi = i * 128 + tid;
            cp16(dst + gi * 16, sa + gi);
        }
#pragma unroll
        for (int kk = 0; kk < 2; kk++) {
            int kt = 2 * tt + kk;
            const uint4* sbp = (const uint4*)g_wt
                             + ((size_t)(h * KT_TILES + kt) * 128 + nh) * 4;
#pragma unroll
            for (int i = 0; i < 2; i++) {
                int gi = i * 128 + tid;           // 256 granules per slab
                cp16(dst + 16384 + kk * 4096 + gi * 16, sbp + gi);
            }
        }
    };

    cp_tile(0, 0); CP_COMMIT();
    cp_tile(1, 1); CP_COMMIT();

    float acc[4][4][4];
#pragma unroll
    for (int mt = 0; mt < 4; mt++)
#pragma unroll
        for (int nt = 0; nt < 4; nt++)
#pragma unroll
            for (int e = 0; e < 4; e++) acc[mt][nt][e] = 0.f;

    CP_WAIT(1);
    __syncthreads();

    for (int tt = 0; tt < TT; tt++) {
        const int st = tt % 3;
        if (tt + 2 < TT) {
            cp_tile(tt + 2, (tt + 2) % 3);
            CP_COMMIT();
        }

#pragma unroll
        for (int sub = 0; sub < 2; sub++) {
            const uint32_t* AS = smu + st * SM_STAGE + sub * 2048;
            const uint32_t* BS = smu + st * SM_STAGE + 4096 + sub * 1024;
            uint32_t afA[4][4], afB[4][4];
#pragma unroll
            for (int mt = 0; mt < 4; mt++) {
                int r = wrow + mt * 16 + grp;
                int pg = (tig ^ ((r >> 1) & 3)) * 4;
                *(uint4*)&afA[mt][0] = *(const uint4*)&AS[r * 16 + pg];
                *(uint4*)&afB[mt][0] = *(const uint4*)&AS[(r + 8) * 16 + pg];
            }
            uint32_t bf[4][4];
#pragma unroll
            for (int nt = 0; nt < 4; nt++) {
                int n = wcol + nt * 8 + grp;      // local 0..63
                int pg = (tig ^ ((n >> 1) & 3)) * 4;
                *(uint4*)&bf[nt][0] = *(const uint4*)&BS[n * 16 + pg];
            }
#pragma unroll
            for (int s = 0; s < 2; s++) {
#pragma unroll
                for (int mt = 0; mt < 4; mt++) {
                    uint32_t a[4] = { afA[mt][2 * s], afB[mt][2 * s],
                                      afA[mt][2 * s + 1], afB[mt][2 * s + 1] };
#pragma unroll
                    for (int nt = 0; nt < 4; nt++) {
                        uint32_t b[2] = { bf[nt][2 * s], bf[nt][2 * s + 1] };
                        mma_f16(acc[mt][nt], a, b);
                    }
                }
            }
        }

        if (tt + 2 < TT) { CP_WAIT(1); } else { CP_WAIT(0); }
        __syncthreads();
    }

    // epilogue
#pragma unroll
    for (int mt = 0; mt < 4; mt++) {
        int gr = row_base + wrow + mt * 16 + grp;
#pragma unroll
        for (int nt = 0; nt < 4; nt++) {
            int gc = col_base + wcol + nt * 8 + tig * 2;
            float2 bb = *(const float2*)&bias[gc];
            float2 v0; v0.x = acc[mt][nt][0] + bb.x; v0.y = acc[mt][nt][1] + bb.y;
            *(float2*)&out[(size_t)gr * OUT_DIM + gc] = v0;
            float2 v1; v1.x = acc[mt][nt][2] + bb.x; v1.y = acc[mt][nt][3] + bb.y;
            *(float2*)&out[(size_t)(gr + 8) * OUT_DIM + gc] = v1;
        }
    }
}

// ---------------------------------------------------------------------------
// Launch. Inputs: x_metric, x_log, y(unused), se_w1, se_w2, align_w, align_b.
// ---------------------------------------------------------------------------
extern "C" void kernel_launch(void* const* d_in, const int* in_sizes, int n_in,
                              void* d_out, int out_size)
{
    const float* xm = (const float*)d_in[0];
    const float* xl = (const float*)d_in[1];
    const float* w1 = (const float*)d_in[3];
    const float* w2 = (const float*)d_in[4];
    const float* aw = (const float*)d_in[5];
    const float* ab = (const float*)d_in[6];
    float* out = (float*)d_out;

    const int smem_bytes = SM_U32 * 4;   // 73728
    cudaFuncSetAttribute(gemm_mma, cudaFuncAttributeMaxDynamicSharedMemorySize, smem_bytes);

    gatea_kernel<<<ROWS_TOT / 8, 128>>>(xm, xl, w1, w2);
    wprep_kernel<<<(2 * KT_TILES * 128 * 4) / 256, 256>>>(aw);
    dim3 grid(ROWS_TOT / 128, 4);
    gemm_mma<<<grid, 128, smem_bytes>>>(ab, out);
}